// round 16
// baseline (speedup 1.0000x reference)
#include <cuda_runtime.h>
#include <cuda_fp16.h>
#include <cstdint>
#include <cstddef>

#define N_NODES   100000
#define N_EDGES   1600000
#define IN_DIM    256
#define HIDDEN    128
#define N_CLASSES 40

#define SCAN_B 1024
#define NBLK   ((N_NODES + SCAN_B - 1) / SCAN_B)   // 98

// ---------------- static device scratch (no allocations allowed) ----------------
__device__ __align__(16) float g_dinv[N_NODES];
__device__ int  g_cnt[N_NODES];
__device__ int  g_rowptr[N_NODES + 1];
__device__ int  g_cursor[N_NODES];
__device__ int  g_bsum[NBLK];
__device__ int  g_cidx[N_EDGES];
__device__ __align__(16) __half g_P1h[(size_t)N_NODES * HIDDEN];     // fp16 messages L1
__device__ __align__(16) __half g_X1h[(size_t)N_NODES * HIDDEN];     // fp16 hidden acts
__device__ __align__(16) __half g_P2h[(size_t)N_NODES * N_CLASSES];  // fp16 messages L2
__device__ __align__(16) float g_Wt[HIDDEN * IN_DIM];     // W1^T [n][k], tf32-rounded
__device__ __align__(16) float g_W2t[N_CLASSES * HIDDEN]; // W2^T [n][k], tf32-rounded

// ---------------- CSR build ----------------
__global__ void hist_kernel(const int* __restrict__ ei) {
    int e = blockIdx.x * blockDim.x + threadIdx.x;
    if (e < N_EDGES) atomicAdd(&g_cnt[ei[N_EDGES + e]], 1);
}

__global__ void scan1_kernel() {
    __shared__ int sh[SCAN_B];
    int tid = threadIdx.x;
    int i = blockIdx.x * SCAN_B + tid;
    int v = (i < N_NODES) ? g_cnt[i] : 0;
    sh[tid] = v;
    __syncthreads();
#pragma unroll
    for (int off = 1; off < SCAN_B; off <<= 1) {
        int t = (tid >= off) ? sh[tid - off] : 0;
        __syncthreads();
        sh[tid] += t;
        __syncthreads();
    }
    if (i < N_NODES) g_rowptr[i] = sh[tid] - v;
    if (tid == SCAN_B - 1) g_bsum[blockIdx.x] = sh[tid];
}

__global__ void scan2_kernel() {
    __shared__ int wsum[4];
    int t = threadIdx.x;
    int v = (t < NBLK) ? g_bsum[t] : 0;
    int x = v;
#pragma unroll
    for (int off = 1; off < 32; off <<= 1) {
        int y = __shfl_up_sync(0xFFFFFFFFu, x, off);
        if ((t & 31) >= off) x += y;
    }
    if ((t & 31) == 31) wsum[t >> 5] = x;
    __syncthreads();
    int add = 0;
#pragma unroll
    for (int w = 0; w < 4; w++)
        if (w < (t >> 5)) add += wsum[w];
    if (t < NBLK) g_bsum[t] = x - v + add;
}

__global__ void scan3_kernel() {
    int i = blockIdx.x * blockDim.x + threadIdx.x;
    if (i < N_NODES) {
        int r = g_rowptr[i] + g_bsum[i / SCAN_B];
        g_rowptr[i] = r;
        g_cursor[i] = r;
        g_dinv[i] = rsqrtf((float)g_cnt[i] + 1.0f);
    }
    if (i == 0) g_rowptr[N_NODES] = N_EDGES;
}

__global__ void place_kernel(const int* __restrict__ ei) {
    int e = blockIdx.x * blockDim.x + threadIdx.x;
    if (e < N_EDGES) {
        int s = ei[e];
        int d = ei[N_EDGES + e];
        int pos = atomicAdd(&g_cursor[d], 1);
        g_cidx[pos] = s;
    }
}

// ---------------- weight prep ----------------
__device__ __forceinline__ float to_tf32(float f) {
    uint32_t r;
    asm("cvt.rna.tf32.f32 %0, %1;" : "=r"(r) : "f"(f));
    return __uint_as_float(r);
}

__global__ void wt_kernel(const float* __restrict__ W1) {
    int i = blockIdx.x * blockDim.x + threadIdx.x;
    if (i >= HIDDEN * IN_DIM) return;
    int n = i / IN_DIM;
    int k = i % IN_DIM;
    g_Wt[i] = to_tf32(W1[(size_t)k * HIDDEN + n]);
}

__global__ void w2t_kernel(const float* __restrict__ W2) {
    int i = blockIdx.x * blockDim.x + threadIdx.x;
    if (i >= N_CLASSES * HIDDEN) return;
    int n = i / HIDDEN;
    int k = i % HIDDEN;
    g_W2t[i] = to_tf32(W2[(size_t)k * N_CLASSES + n]);
}

// ---------------- tf32 mma helper ----------------
// k-order note: A and B fragments both use the plain uint2 at column kk+2*tg —
// a common permutation of the k-sum, numerically identical to canonical order.
__device__ __forceinline__ void mma_tf32(float c[4], uint32_t a0, uint32_t a1, uint32_t a2,
                                         uint32_t a3, uint32_t b0, uint32_t b1) {
    asm volatile(
        "mma.sync.aligned.m16n8k8.row.col.f32.tf32.tf32.f32 "
        "{%0,%1,%2,%3}, {%4,%5,%6,%7}, {%8,%9}, {%0,%1,%2,%3};"
        : "+f"(c[0]), "+f"(c[1]), "+f"(c[2]), "+f"(c[3])
        : "r"(a0), "r"(a1), "r"(a2), "r"(a3), "r"(b0), "r"(b1));
}

__device__ __forceinline__ uint32_t smem_u32(const void* p) {
    uint32_t a;
    asm("{ .reg .u64 t; cvta.to.shared.u64 t, %1; cvt.u32.u64 %0, t; }" : "=r"(a) : "l"(p));
    return a;
}

__device__ __forceinline__ uint32_t f2u_tf32(float f) {
    uint32_t r;
    asm("cvt.rna.tf32.f32 %0, %1;" : "=r"(r) : "f"(f));
    return r;
}

// ================= layer-1 tf32 GEMM: P1h = half(X @ W1), cp.async pipelined =================
#define PITCHF 40              // pitch ≡ 8 (mod 32) -> conflict-free LDS.64 fragment loads
#define CHUNKF (128 * PITCHF)  // floats per chunk buffer (20 KB)

__global__ void __launch_bounds__(256, 2) gemm1_mma_kernel(const float* __restrict__ X,
                                                           __half* __restrict__ P) {
    extern __shared__ float sm[];
    float* AsB[2] = { sm, sm + CHUNKF };
    float* BsB[2] = { sm + 2 * CHUNKF, sm + 3 * CHUNKF };

    const int tid = threadIdx.x, lane = tid & 31, wid = tid >> 5;
    const int warpM = wid & 3;
    const int warpN = wid >> 2;
    const int rowBase = blockIdx.x * 128;
    const int gq = lane >> 2;
    const int tg = lane & 3;

    float acc[2][8][4];
#pragma unroll
    for (int m = 0; m < 2; m++)
#pragma unroll
        for (int n = 0; n < 8; n++)
#pragma unroll
            for (int r = 0; r < 4; r++) acc[m][n][r] = 0.0f;

    auto prefetch = [&](int c) {
        int k0 = c * 32;
        int buf = c & 1;
        uint32_t abase = smem_u32(AsB[buf]);
        uint32_t bbase = smem_u32(BsB[buf]);
#pragma unroll
        for (int j = tid; j < 1024; j += 256) {
            int r = j >> 3, col = (j & 7) * 4;
            int gr = rowBase + r;
            int ok = (gr < N_NODES);
            const float* src = X + (size_t)(ok ? gr : 0) * IN_DIM + k0 + col;
            int sz = ok ? 16 : 0;   // zero-fill OOB rows
            asm volatile("cp.async.cg.shared.global [%0], [%1], 16, %2;"
                         :: "r"(abase + (uint32_t)(r * PITCHF + col) * 4), "l"(src), "r"(sz));
        }
#pragma unroll
        for (int j = tid; j < 1024; j += 256) {
            int r = j >> 3, col = (j & 7) * 4;
            const float* src = g_Wt + (size_t)r * IN_DIM + k0 + col;
            asm volatile("cp.async.cg.shared.global [%0], [%1], 16;"
                         :: "r"(bbase + (uint32_t)(r * PITCHF + col) * 4), "l"(src));
        }
        asm volatile("cp.async.commit_group;" ::: "memory");
    };

    prefetch(0);
    for (int c = 0; c < 8; c++) {
        if (c < 7) {
            prefetch(c + 1);
            asm volatile("cp.async.wait_group 1;" ::: "memory");
        } else {
            asm volatile("cp.async.wait_group 0;" ::: "memory");
        }
        __syncthreads();

        const float* As = AsB[c & 1];
        const float* Bs = BsB[c & 1];
#pragma unroll
        for (int kk = 0; kk < 32; kk += 8) {
            uint32_t bf[8][2];
#pragma unroll
            for (int nt = 0; nt < 8; nt++) {
                int n = warpN * 64 + nt * 8 + gq;
                uint2 bb = *reinterpret_cast<const uint2*>(Bs + n * PITCHF + kk + 2 * tg);
                bf[nt][0] = bb.x;
                bf[nt][1] = bb.y;
            }
#pragma unroll
            for (int mt = 0; mt < 2; mt++) {
                int r0 = warpM * 32 + mt * 16 + gq;
                float2 aa = *reinterpret_cast<const float2*>(As + r0 * PITCHF + kk + 2 * tg);
                float2 a8 = *reinterpret_cast<const float2*>(As + (r0 + 8) * PITCHF + kk + 2 * tg);
                uint32_t a0 = f2u_tf32(aa.x);
                uint32_t a1 = f2u_tf32(a8.x);
                uint32_t a2 = f2u_tf32(aa.y);
                uint32_t a3 = f2u_tf32(a8.y);
#pragma unroll
                for (int nt = 0; nt < 8; nt++)
                    mma_tf32(acc[mt][nt], a0, a1, a2, a3, bf[nt][0], bf[nt][1]);
            }
        }
        __syncthreads();
    }

    // epilogue: write UNSCALED P1 as fp16 (dinv applied in agg1)
#pragma unroll
    for (int mt = 0; mt < 2; mt++) {
        int r0 = rowBase + warpM * 32 + mt * 16 + gq;
        int r1 = r0 + 8;
#pragma unroll
        for (int nt = 0; nt < 8; nt++) {
            int col = warpN * 64 + nt * 8 + tg * 2;
            if (r0 < N_NODES)
                *reinterpret_cast<__half2*>(P + (size_t)r0 * HIDDEN + col) =
                    __floats2half2_rn(acc[mt][nt][0], acc[mt][nt][1]);
            if (r1 < N_NODES)
                *reinterpret_cast<__half2*>(P + (size_t)r1 * HIDDEN + col) =
                    __floats2half2_rn(acc[mt][nt][2], acc[mt][nt][3]);
        }
    }
}

// ================= layer-2 tf32 GEMM: P2h = half(dinv ⊙ (X1h @ W2)) =================
#define PITCHA2 40  // As pitch ≡ 8 (mod 32) -> conflict-free LDS.64 frags
#define PITCH2  136 // Bs pitch ≡ 8 (mod 32)

__global__ void __launch_bounds__(256) gemm2_mma_kernel(const __half* __restrict__ X1,
                                                        __half* __restrict__ P) {
    extern __shared__ float dynsm[];
    float* As = dynsm;                       // 256 * PITCHA2
    float* Bs = dynsm + 256 * PITCHA2;       // 40 * PITCH2

    const int tid = threadIdx.x, lane = tid & 31, wid = tid >> 5;
    const int rowBase = blockIdx.x * 256;
    const int gq = lane >> 2;
    const int tg = lane & 3;

    for (int i = tid; i < (N_CLASSES * HIDDEN) / 4; i += 256) {
        int n  = i >> 5;
        int c4 = (i & 31) * 4;
        *reinterpret_cast<float4*>(Bs + n * PITCH2 + c4) =
            *reinterpret_cast<const float4*>(g_W2t + (size_t)n * HIDDEN + c4);
    }

    float acc[2][5][4];
#pragma unroll
    for (int m = 0; m < 2; m++)
#pragma unroll
        for (int n = 0; n < 5; n++)
#pragma unroll
            for (int r = 0; r < 4; r++) acc[m][n][r] = 0.0f;

    for (int k0 = 0; k0 < HIDDEN; k0 += 32) {
        // stage A: fp16 -> fp32 convert (fp16 values are exactly tf32-representable)
#pragma unroll
        for (int i = tid; i < 1024; i += 256) {   // 256 rows x 4 uint4 (8 halves each)
            int r  = i >> 2;
            int c8 = (i & 3) * 8;
            int gr = rowBase + r;
            float4 lo = make_float4(0.f, 0.f, 0.f, 0.f);
            float4 hi = make_float4(0.f, 0.f, 0.f, 0.f);
            if (gr < N_NODES) {
                const __half2* src = reinterpret_cast<const __half2*>(
                    X1 + (size_t)gr * HIDDEN + k0 + c8);
                float2 p0 = __half22float2(src[0]);
                float2 p1 = __half22float2(src[1]);
                float2 p2 = __half22float2(src[2]);
                float2 p3 = __half22float2(src[3]);
                lo = make_float4(p0.x, p0.y, p1.x, p1.y);
                hi = make_float4(p2.x, p2.y, p3.x, p3.y);
            }
            *reinterpret_cast<float4*>(As + r * PITCHA2 + c8)     = lo;
            *reinterpret_cast<float4*>(As + r * PITCHA2 + c8 + 4) = hi;
        }
        __syncthreads();

#pragma unroll
        for (int kk = 0; kk < 32; kk += 8) {
            uint32_t bf[5][2];
#pragma unroll
            for (int nt = 0; nt < 5; nt++) {
                int n = nt * 8 + gq;
                uint2 bb = *reinterpret_cast<const uint2*>(Bs + n * PITCH2 + k0 + kk + 2 * tg);
                bf[nt][0] = bb.x;
                bf[nt][1] = bb.y;
            }
#pragma unroll
            for (int mt = 0; mt < 2; mt++) {
                int r0 = wid * 32 + mt * 16 + gq;
                uint2 aa = *reinterpret_cast<const uint2*>(As + r0 * PITCHA2 + kk + 2 * tg);
                uint2 a8 = *reinterpret_cast<const uint2*>(As + (r0 + 8) * PITCHA2 + kk + 2 * tg);
#pragma unroll
                for (int nt = 0; nt < 5; nt++)
                    mma_tf32(acc[mt][nt], aa.x, a8.x, aa.y, a8.y, bf[nt][0], bf[nt][1]);
            }
        }
        __syncthreads();
    }

#pragma unroll
    for (int mt = 0; mt < 2; mt++) {
        int r0 = rowBase + wid * 32 + mt * 16 + gq;
        int r1 = r0 + 8;
        float d0 = (r0 < N_NODES) ? g_dinv[r0] : 0.f;
        float d1 = (r1 < N_NODES) ? g_dinv[r1] : 0.f;
#pragma unroll
        for (int nt = 0; nt < 5; nt++) {
            int col = nt * 8 + tg * 2;
            if (r0 < N_NODES)
                *reinterpret_cast<__half2*>(P + (size_t)r0 * N_CLASSES + col) =
                    __floats2half2_rn(acc[mt][nt][0] * d0, acc[mt][nt][1] * d0);
            if (r1 < N_NODES)
                *reinterpret_cast<__half2*>(P + (size_t)r1 * N_CLASSES + col) =
                    __floats2half2_rn(acc[mt][nt][2] * d1, acc[mt][nt][3] * d1);
        }
    }
}

// ---------------- layer-1 aggregation (warp per node, fp16 gathers, unroll-2) ----------------
// X1h[n] = half( relu( dinv[n]*( sum_s dinv[s]*P1[s] + dinv[n]*P1[n] ) + b1 ) )
__global__ void agg1_kernel(const float* __restrict__ b1) {
    int t = blockIdx.x * blockDim.x + threadIdx.x;
    int n = t >> 5;
    int c = t & 31;
    if (n >= N_NODES) return;

    int beg = g_rowptr[n];
    int end = g_rowptr[n + 1];
    float dn = g_dinv[n];

    __half2 h[2];
    *reinterpret_cast<uint2*>(h) =
        *reinterpret_cast<const uint2*>(g_P1h + (size_t)n * HIDDEN + c * 4);
    float2 f0 = __half22float2(h[0]);
    float2 f1 = __half22float2(h[1]);
    float4 acc = make_float4(f0.x * dn, f0.y * dn, f1.x * dn, f1.y * dn);

    int e = beg;
    for (; e + 1 < end; e += 2) {     // two independent gathers in flight
        int s0 = g_cidx[e];
        int s1 = g_cidx[e + 1];
        float ds0 = g_dinv[s0];
        float ds1 = g_dinv[s1];
        __half2 ha[2], hb[2];
        *reinterpret_cast<uint2*>(ha) =
            *reinterpret_cast<const uint2*>(g_P1h + (size_t)s0 * HIDDEN + c * 4);
        *reinterpret_cast<uint2*>(hb) =
            *reinterpret_cast<const uint2*>(g_P1h + (size_t)s1 * HIDDEN + c * 4);
        float2 a0 = __half22float2(ha[0]), a1 = __half22float2(ha[1]);
        float2 b0 = __half22float2(hb[0]), b1 = __half22float2(hb[1]);
        acc.x = fmaf(a0.x, ds0, fmaf(b0.x, ds1, acc.x));
        acc.y = fmaf(a0.y, ds0, fmaf(b0.y, ds1, acc.y));
        acc.z = fmaf(a1.x, ds0, fmaf(b1.x, ds1, acc.z));
        acc.w = fmaf(a1.y, ds0, fmaf(b1.y, ds1, acc.w));
    }
    if (e < end) {
        int s = g_cidx[e];
        float ds = g_dinv[s];
        *reinterpret_cast<uint2*>(h) =
            *reinterpret_cast<const uint2*>(g_P1h + (size_t)s * HIDDEN + c * 4);
        f0 = __half22float2(h[0]);
        f1 = __half22float2(h[1]);
        acc.x = fmaf(f0.x, ds, acc.x);
        acc.y = fmaf(f0.y, ds, acc.y);
        acc.z = fmaf(f1.x, ds, acc.z);
        acc.w = fmaf(f1.y, ds, acc.w);
    }
    float4 bb = *reinterpret_cast<const float4*>(b1 + c * 4);
    __half2 o[2];
    o[0] = __floats2half2_rn(fmaxf(fmaf(acc.x, dn, bb.x), 0.0f),
                             fmaxf(fmaf(acc.y, dn, bb.y), 0.0f));
    o[1] = __floats2half2_rn(fmaxf(fmaf(acc.z, dn, bb.z), 0.0f),
                             fmaxf(fmaf(acc.w, dn, bb.w), 0.0f));
    *reinterpret_cast<uint2*>(g_X1h + (size_t)n * HIDDEN + c * 4) =
        *reinterpret_cast<const uint2*>(o);
}

// ---------------- layer-2 aggregation (10 chunks of 4 cols per node, unroll-2) ----------------
__global__ void agg2_kernel(const float* __restrict__ b2, float* __restrict__ out) {
    int t = blockIdx.x * blockDim.x + threadIdx.x;
    int n = t / 10;
    int c = t % 10;
    if (n >= N_NODES) return;

    int beg = g_rowptr[n];
    int end = g_rowptr[n + 1];

    __half2 h[2];
    *reinterpret_cast<uint2*>(h) =
        *reinterpret_cast<const uint2*>(g_P2h + (size_t)n * N_CLASSES + c * 4);
    float2 f0 = __half22float2(h[0]);
    float2 f1 = __half22float2(h[1]);
    float4 acc = make_float4(f0.x, f0.y, f1.x, f1.y);

    int e = beg;
    for (; e + 1 < end; e += 2) {
        int s0 = g_cidx[e];
        int s1 = g_cidx[e + 1];
        __half2 ha[2], hb[2];
        *reinterpret_cast<uint2*>(ha) =
            *reinterpret_cast<const uint2*>(g_P2h + (size_t)s0 * N_CLASSES + c * 4);
        *reinterpret_cast<uint2*>(hb) =
            *reinterpret_cast<const uint2*>(g_P2h + (size_t)s1 * N_CLASSES + c * 4);
        float2 a0 = __half22float2(ha[0]), a1 = __half22float2(ha[1]);
        float2 b0 = __half22float2(hb[0]), b1 = __half22float2(hb[1]);
        acc.x += a0.x + b0.x;
        acc.y += a0.y + b0.y;
        acc.z += a1.x + b1.x;
        acc.w += a1.y + b1.y;
    }
    if (e < end) {
        int s = g_cidx[e];
        *reinterpret_cast<uint2*>(h) =
            *reinterpret_cast<const uint2*>(g_P2h + (size_t)s * N_CLASSES + c * 4);
        f0 = __half22float2(h[0]);
        f1 = __half22float2(h[1]);
        acc.x += f0.x; acc.y += f0.y; acc.z += f1.x; acc.w += f1.y;
    }
    float sc = g_dinv[n];
    float4 bb = *reinterpret_cast<const float4*>(b2 + c * 4);
    float4 o;
    o.x = fmaf(acc.x, sc, bb.x);
    o.y = fmaf(acc.y, sc, bb.y);
    o.z = fmaf(acc.z, sc, bb.z);
    o.w = fmaf(acc.w, sc, bb.w);
    *reinterpret_cast<float4*>(out + (size_t)n * N_CLASSES + c * 4) = o;
}

// ---------------- launch ----------------
// Parallel graph branches via stream fork/join:
//   main: wt -> gemm1                               (tensor/smem-bound)
//   side: memset -> hist -> scans -> place -> w2t   (L2-atomic-bound)
// Joined before agg1.
extern "C" void kernel_launch(void* const* d_in, const int* in_sizes, int n_in,
                              void* d_out, int out_size) {
    const float* x  = (const float*)d_in[0];
    const int*   ei = (const int*)d_in[1];     // int32 (JAX x64 disabled)
    const float* W1 = (const float*)d_in[2];
    const float* b1 = (const float*)d_in[3];
    const float* W2 = (const float*)d_in[4];
    const float* b2 = (const float*)d_in[5];
    float* out = (float*)d_out;

    __half *p1, *p2, *x1;
    int* cnt;
    cudaGetSymbolAddress((void**)&p1, g_P1h);
    cudaGetSymbolAddress((void**)&x1, g_X1h);
    cudaGetSymbolAddress((void**)&p2, g_P2h);
    cudaGetSymbolAddress((void**)&cnt, g_cnt);

    const int T = 256;
    const int smem1 = 4 * CHUNKF * sizeof(float);                        // 81920
    const int smem2 = (256 * PITCHA2 + N_CLASSES * PITCH2) * sizeof(float);
    cudaFuncSetAttribute(gemm1_mma_kernel, cudaFuncAttributeMaxDynamicSharedMemorySize, smem1);
    cudaFuncSetAttribute(gemm2_mma_kernel, cudaFuncAttributeMaxDynamicSharedMemorySize, smem2);

    cudaStream_t side;
    cudaStreamCreateWithFlags(&side, cudaStreamNonBlocking);
    cudaEvent_t evFork, evJoin;
    cudaEventCreateWithFlags(&evFork, cudaEventDisableTiming);
    cudaEventCreateWithFlags(&evJoin, cudaEventDisableTiming);

    cudaEventRecord(evFork, 0);
    cudaStreamWaitEvent(side, evFork, 0);

    // side branch: CSR build + dinv + W2 prep
    cudaMemsetAsync(cnt, 0, N_NODES * sizeof(int), side);
    hist_kernel<<<(N_EDGES + T - 1) / T, T, 0, side>>>(ei);
    scan1_kernel<<<NBLK, SCAN_B, 0, side>>>();
    scan2_kernel<<<1, 128, 0, side>>>();
    scan3_kernel<<<(N_NODES + T - 1) / T, T, 0, side>>>();
    place_kernel<<<(N_EDGES + T - 1) / T, T, 0, side>>>(ei);
    w2t_kernel<<<(N_CLASSES * HIDDEN + T - 1) / T, T, 0, side>>>(W2);
    cudaEventRecord(evJoin, side);

    // main branch: W1 prep + layer-1 GEMM
    wt_kernel<<<(HIDDEN * IN_DIM + T - 1) / T, T>>>(W1);
    gemm1_mma_kernel<<<(N_NODES + 127) / 128, 256, smem1>>>(x, p1);

    // join: aggregation needs both branches
    cudaStreamWaitEvent(0, evJoin, 0);

    agg1_kernel<<<(N_NODES * 32 + T - 1) / T, T>>>(b1);
    gemm2_mma_kernel<<<(N_NODES + 255) / 256, 256, smem2>>>(x1, p2);
    agg2_kernel<<<(N_NODES * 10 + T - 1) / T, T>>>(b2, out);
}

// round 17
// speedup vs baseline: 1.0554x; 1.0554x over previous
#include <cuda_runtime.h>
#include <cuda_fp16.h>
#include <cstdint>
#include <cstddef>

#define N_NODES   100000
#define N_EDGES   1600000
#define IN_DIM    256
#define HIDDEN    128
#define N_CLASSES 40

#define SCAN_B 1024
#define NBLK   ((N_NODES + SCAN_B - 1) / SCAN_B)   // 98

// ---------------- static device scratch (no allocations allowed) ----------------
__device__ __align__(16) float g_dinv[N_NODES];
__device__ int  g_cnt[N_NODES];
__device__ int  g_rowptr[N_NODES + 1];
__device__ int  g_cursor[N_NODES];
__device__ int  g_bsum[NBLK];
__device__ int  g_cidx[N_EDGES];
__device__ __align__(16) __half g_P1h[(size_t)N_NODES * HIDDEN];     // fp16 messages L1
__device__ __align__(16) __half g_X1h[(size_t)N_NODES * HIDDEN];     // fp16 hidden acts
__device__ __align__(16) __half g_P2h[(size_t)N_NODES * N_CLASSES];  // fp16 messages L2
__device__ __align__(16) float g_Wt[HIDDEN * IN_DIM];     // W1^T [n][k], tf32-rounded
__device__ __align__(16) float g_W2t[N_CLASSES * HIDDEN]; // W2^T [n][k], tf32-rounded

// ---------------- CSR build ----------------
__global__ void hist_kernel(const int* __restrict__ ei) {
    int e = blockIdx.x * blockDim.x + threadIdx.x;
    if (e < N_EDGES) atomicAdd(&g_cnt[ei[N_EDGES + e]], 1);
}

__global__ void scan1_kernel() {
    __shared__ int sh[SCAN_B];
    int tid = threadIdx.x;
    int i = blockIdx.x * SCAN_B + tid;
    int v = (i < N_NODES) ? g_cnt[i] : 0;
    sh[tid] = v;
    __syncthreads();
#pragma unroll
    for (int off = 1; off < SCAN_B; off <<= 1) {
        int t = (tid >= off) ? sh[tid - off] : 0;
        __syncthreads();
        sh[tid] += t;
        __syncthreads();
    }
    if (i < N_NODES) g_rowptr[i] = sh[tid] - v;
    if (tid == SCAN_B - 1) g_bsum[blockIdx.x] = sh[tid];
}

__global__ void scan2_kernel() {
    __shared__ int wsum[4];
    int t = threadIdx.x;
    int v = (t < NBLK) ? g_bsum[t] : 0;
    int x = v;
#pragma unroll
    for (int off = 1; off < 32; off <<= 1) {
        int y = __shfl_up_sync(0xFFFFFFFFu, x, off);
        if ((t & 31) >= off) x += y;
    }
    if ((t & 31) == 31) wsum[t >> 5] = x;
    __syncthreads();
    int add = 0;
#pragma unroll
    for (int w = 0; w < 4; w++)
        if (w < (t >> 5)) add += wsum[w];
    if (t < NBLK) g_bsum[t] = x - v + add;
}

__global__ void scan3_kernel() {
    int i = blockIdx.x * blockDim.x + threadIdx.x;
    if (i < N_NODES) {
        int r = g_rowptr[i] + g_bsum[i / SCAN_B];
        g_rowptr[i] = r;
        g_cursor[i] = r;
        g_dinv[i] = rsqrtf((float)g_cnt[i] + 1.0f);
    }
    if (i == 0) g_rowptr[N_NODES] = N_EDGES;
}

__global__ void place_kernel(const int* __restrict__ ei) {
    int e = blockIdx.x * blockDim.x + threadIdx.x;
    if (e < N_EDGES) {
        int s = ei[e];
        int d = ei[N_EDGES + e];
        int pos = atomicAdd(&g_cursor[d], 1);
        g_cidx[pos] = s;
    }
}

// ---------------- weight prep ----------------
__device__ __forceinline__ float to_tf32(float f) {
    uint32_t r;
    asm("cvt.rna.tf32.f32 %0, %1;" : "=r"(r) : "f"(f));
    return __uint_as_float(r);
}

__global__ void wt_kernel(const float* __restrict__ W1) {
    int i = blockIdx.x * blockDim.x + threadIdx.x;
    if (i >= HIDDEN * IN_DIM) return;
    int n = i / IN_DIM;
    int k = i % IN_DIM;
    g_Wt[i] = to_tf32(W1[(size_t)k * HIDDEN + n]);
}

__global__ void w2t_kernel(const float* __restrict__ W2) {
    int i = blockIdx.x * blockDim.x + threadIdx.x;
    if (i >= N_CLASSES * HIDDEN) return;
    int n = i / HIDDEN;
    int k = i % HIDDEN;
    g_W2t[i] = to_tf32(W2[(size_t)k * N_CLASSES + n]);
}

// ---------------- tf32 mma helper ----------------
// k-order note: A and B fragments both use the plain uint2 at column kk+2*tg —
// a common permutation of the k-sum, numerically identical to canonical order.
__device__ __forceinline__ void mma_tf32(float c[4], uint32_t a0, uint32_t a1, uint32_t a2,
                                         uint32_t a3, uint32_t b0, uint32_t b1) {
    asm volatile(
        "mma.sync.aligned.m16n8k8.row.col.f32.tf32.tf32.f32 "
        "{%0,%1,%2,%3}, {%4,%5,%6,%7}, {%8,%9}, {%0,%1,%2,%3};"
        : "+f"(c[0]), "+f"(c[1]), "+f"(c[2]), "+f"(c[3])
        : "r"(a0), "r"(a1), "r"(a2), "r"(a3), "r"(b0), "r"(b1));
}

__device__ __forceinline__ uint32_t smem_u32(const void* p) {
    uint32_t a;
    asm("{ .reg .u64 t; cvta.to.shared.u64 t, %1; cvt.u32.u64 %0, t; }" : "=r"(a) : "l"(p));
    return a;
}

__device__ __forceinline__ uint32_t f2u_tf32(float f) {
    uint32_t r;
    asm("cvt.rna.tf32.f32 %0, %1;" : "=r"(r) : "f"(f));
    return r;
}

// ================= layer-1 tf32 GEMM: P1h = half(X @ W1), cp.async pipelined =================
#define PITCHF 40              // pitch ≡ 8 (mod 32) -> conflict-free LDS.64 fragment loads
#define CHUNKF (128 * PITCHF)  // floats per chunk buffer (20 KB)

__global__ void __launch_bounds__(256, 2) gemm1_mma_kernel(const float* __restrict__ X,
                                                           __half* __restrict__ P) {
    extern __shared__ float sm[];
    float* AsB[2] = { sm, sm + CHUNKF };
    float* BsB[2] = { sm + 2 * CHUNKF, sm + 3 * CHUNKF };

    const int tid = threadIdx.x, lane = tid & 31, wid = tid >> 5;
    const int warpM = wid & 3;
    const int warpN = wid >> 2;
    const int rowBase = blockIdx.x * 128;
    const int gq = lane >> 2;
    const int tg = lane & 3;

    float acc[2][8][4];
#pragma unroll
    for (int m = 0; m < 2; m++)
#pragma unroll
        for (int n = 0; n < 8; n++)
#pragma unroll
            for (int r = 0; r < 4; r++) acc[m][n][r] = 0.0f;

    auto prefetch = [&](int c) {
        int k0 = c * 32;
        int buf = c & 1;
        uint32_t abase = smem_u32(AsB[buf]);
        uint32_t bbase = smem_u32(BsB[buf]);
#pragma unroll
        for (int j = tid; j < 1024; j += 256) {
            int r = j >> 3, col = (j & 7) * 4;
            int gr = rowBase + r;
            int ok = (gr < N_NODES);
            const float* src = X + (size_t)(ok ? gr : 0) * IN_DIM + k0 + col;
            int sz = ok ? 16 : 0;   // zero-fill OOB rows
            asm volatile("cp.async.cg.shared.global [%0], [%1], 16, %2;"
                         :: "r"(abase + (uint32_t)(r * PITCHF + col) * 4), "l"(src), "r"(sz));
        }
#pragma unroll
        for (int j = tid; j < 1024; j += 256) {
            int r = j >> 3, col = (j & 7) * 4;
            const float* src = g_Wt + (size_t)r * IN_DIM + k0 + col;
            asm volatile("cp.async.cg.shared.global [%0], [%1], 16;"
                         :: "r"(bbase + (uint32_t)(r * PITCHF + col) * 4), "l"(src));
        }
        asm volatile("cp.async.commit_group;" ::: "memory");
    };

    prefetch(0);
    for (int c = 0; c < 8; c++) {
        if (c < 7) {
            prefetch(c + 1);
            asm volatile("cp.async.wait_group 1;" ::: "memory");
        } else {
            asm volatile("cp.async.wait_group 0;" ::: "memory");
        }
        __syncthreads();

        const float* As = AsB[c & 1];
        const float* Bs = BsB[c & 1];
#pragma unroll
        for (int kk = 0; kk < 32; kk += 8) {
            uint32_t bf[8][2];
#pragma unroll
            for (int nt = 0; nt < 8; nt++) {
                int n = warpN * 64 + nt * 8 + gq;
                uint2 bb = *reinterpret_cast<const uint2*>(Bs + n * PITCHF + kk + 2 * tg);
                bf[nt][0] = bb.x;
                bf[nt][1] = bb.y;
            }
#pragma unroll
            for (int mt = 0; mt < 2; mt++) {
                int r0 = warpM * 32 + mt * 16 + gq;
                float2 aa = *reinterpret_cast<const float2*>(As + r0 * PITCHF + kk + 2 * tg);
                float2 a8 = *reinterpret_cast<const float2*>(As + (r0 + 8) * PITCHF + kk + 2 * tg);
                uint32_t a0 = f2u_tf32(aa.x);
                uint32_t a1 = f2u_tf32(a8.x);
                uint32_t a2 = f2u_tf32(aa.y);
                uint32_t a3 = f2u_tf32(a8.y);
#pragma unroll
                for (int nt = 0; nt < 8; nt++)
                    mma_tf32(acc[mt][nt], a0, a1, a2, a3, bf[nt][0], bf[nt][1]);
            }
        }
        __syncthreads();
    }

    // epilogue: write UNSCALED P1 as fp16 (dinv applied in agg1)
#pragma unroll
    for (int mt = 0; mt < 2; mt++) {
        int r0 = rowBase + warpM * 32 + mt * 16 + gq;
        int r1 = r0 + 8;
#pragma unroll
        for (int nt = 0; nt < 8; nt++) {
            int col = warpN * 64 + nt * 8 + tg * 2;
            if (r0 < N_NODES)
                *reinterpret_cast<__half2*>(P + (size_t)r0 * HIDDEN + col) =
                    __floats2half2_rn(acc[mt][nt][0], acc[mt][nt][1]);
            if (r1 < N_NODES)
                *reinterpret_cast<__half2*>(P + (size_t)r1 * HIDDEN + col) =
                    __floats2half2_rn(acc[mt][nt][2], acc[mt][nt][3]);
        }
    }
}

// ================= layer-2 tf32 GEMM: P2h = half(dinv ⊙ (X1h @ W2)) =================
#define PITCHA2 40  // As pitch ≡ 8 (mod 32) -> conflict-free LDS.64 frags
#define PITCH2  136 // Bs pitch ≡ 8 (mod 32)

__global__ void __launch_bounds__(256) gemm2_mma_kernel(const __half* __restrict__ X1,
                                                        __half* __restrict__ P) {
    extern __shared__ float dynsm[];
    float* As = dynsm;                       // 256 * PITCHA2
    float* Bs = dynsm + 256 * PITCHA2;       // 40 * PITCH2

    const int tid = threadIdx.x, lane = tid & 31, wid = tid >> 5;
    const int rowBase = blockIdx.x * 256;
    const int gq = lane >> 2;
    const int tg = lane & 3;

    for (int i = tid; i < (N_CLASSES * HIDDEN) / 4; i += 256) {
        int n  = i >> 5;
        int c4 = (i & 31) * 4;
        *reinterpret_cast<float4*>(Bs + n * PITCH2 + c4) =
            *reinterpret_cast<const float4*>(g_W2t + (size_t)n * HIDDEN + c4);
    }

    float acc[2][5][4];
#pragma unroll
    for (int m = 0; m < 2; m++)
#pragma unroll
        for (int n = 0; n < 5; n++)
#pragma unroll
            for (int r = 0; r < 4; r++) acc[m][n][r] = 0.0f;

    for (int k0 = 0; k0 < HIDDEN; k0 += 32) {
        // stage A: fp16 -> fp32 convert (fp16 values are exactly tf32-representable)
#pragma unroll
        for (int i = tid; i < 1024; i += 256) {   // 256 rows x 4 uint4 (8 halves each)
            int r  = i >> 2;
            int c8 = (i & 3) * 8;
            int gr = rowBase + r;
            float4 lo = make_float4(0.f, 0.f, 0.f, 0.f);
            float4 hi = make_float4(0.f, 0.f, 0.f, 0.f);
            if (gr < N_NODES) {
                const __half2* src = reinterpret_cast<const __half2*>(
                    X1 + (size_t)gr * HIDDEN + k0 + c8);
                float2 p0 = __half22float2(src[0]);
                float2 p1 = __half22float2(src[1]);
                float2 p2 = __half22float2(src[2]);
                float2 p3 = __half22float2(src[3]);
                lo = make_float4(p0.x, p0.y, p1.x, p1.y);
                hi = make_float4(p2.x, p2.y, p3.x, p3.y);
            }
            *reinterpret_cast<float4*>(As + r * PITCHA2 + c8)     = lo;
            *reinterpret_cast<float4*>(As + r * PITCHA2 + c8 + 4) = hi;
        }
        __syncthreads();

#pragma unroll
        for (int kk = 0; kk < 32; kk += 8) {
            uint32_t bf[5][2];
#pragma unroll
            for (int nt = 0; nt < 5; nt++) {
                int n = nt * 8 + gq;
                uint2 bb = *reinterpret_cast<const uint2*>(Bs + n * PITCH2 + k0 + kk + 2 * tg);
                bf[nt][0] = bb.x;
                bf[nt][1] = bb.y;
            }
#pragma unroll
            for (int mt = 0; mt < 2; mt++) {
                int r0 = wid * 32 + mt * 16 + gq;
                uint2 aa = *reinterpret_cast<const uint2*>(As + r0 * PITCHA2 + kk + 2 * tg);
                uint2 a8 = *reinterpret_cast<const uint2*>(As + (r0 + 8) * PITCHA2 + kk + 2 * tg);
#pragma unroll
                for (int nt = 0; nt < 5; nt++)
                    mma_tf32(acc[mt][nt], aa.x, a8.x, aa.y, a8.y, bf[nt][0], bf[nt][1]);
            }
        }
        __syncthreads();
    }

#pragma unroll
    for (int mt = 0; mt < 2; mt++) {
        int r0 = rowBase + wid * 32 + mt * 16 + gq;
        int r1 = r0 + 8;
        float d0 = (r0 < N_NODES) ? g_dinv[r0] : 0.f;
        float d1 = (r1 < N_NODES) ? g_dinv[r1] : 0.f;
#pragma unroll
        for (int nt = 0; nt < 5; nt++) {
            int col = nt * 8 + tg * 2;
            if (r0 < N_NODES)
                *reinterpret_cast<__half2*>(P + (size_t)r0 * N_CLASSES + col) =
                    __floats2half2_rn(acc[mt][nt][0] * d0, acc[mt][nt][1] * d0);
            if (r1 < N_NODES)
                *reinterpret_cast<__half2*>(P + (size_t)r1 * N_CLASSES + col) =
                    __floats2half2_rn(acc[mt][nt][2] * d1, acc[mt][nt][3] * d1);
        }
    }
}

// ---------------- layer-1 aggregation (warp per node, fp16 gathers; simple loop) ----------------
// X1h[n] = half( relu( dinv[n]*( sum_s dinv[s]*P1[s] + dinv[n]*P1[n] ) + b1 ) )
__global__ void agg1_kernel(const float* __restrict__ b1) {
    int t = blockIdx.x * blockDim.x + threadIdx.x;
    int n = t >> 5;
    int c = t & 31;
    if (n >= N_NODES) return;

    int beg = g_rowptr[n];
    int end = g_rowptr[n + 1];
    float dn = g_dinv[n];

    __half2 h[2];
    *reinterpret_cast<uint2*>(h) =
        *reinterpret_cast<const uint2*>(g_P1h + (size_t)n * HIDDEN + c * 4);
    float2 f0 = __half22float2(h[0]);
    float2 f1 = __half22float2(h[1]);
    float4 acc = make_float4(f0.x * dn, f0.y * dn, f1.x * dn, f1.y * dn);

    for (int e = beg; e < end; e++) {
        int s = g_cidx[e];
        float ds = g_dinv[s];
        *reinterpret_cast<uint2*>(h) =
            *reinterpret_cast<const uint2*>(g_P1h + (size_t)s * HIDDEN + c * 4);
        f0 = __half22float2(h[0]);
        f1 = __half22float2(h[1]);
        acc.x = fmaf(f0.x, ds, acc.x);
        acc.y = fmaf(f0.y, ds, acc.y);
        acc.z = fmaf(f1.x, ds, acc.z);
        acc.w = fmaf(f1.y, ds, acc.w);
    }
    float4 bb = *reinterpret_cast<const float4*>(b1 + c * 4);
    __half2 o[2];
    o[0] = __floats2half2_rn(fmaxf(fmaf(acc.x, dn, bb.x), 0.0f),
                             fmaxf(fmaf(acc.y, dn, bb.y), 0.0f));
    o[1] = __floats2half2_rn(fmaxf(fmaf(acc.z, dn, bb.z), 0.0f),
                             fmaxf(fmaf(acc.w, dn, bb.w), 0.0f));
    *reinterpret_cast<uint2*>(g_X1h + (size_t)n * HIDDEN + c * 4) =
        *reinterpret_cast<const uint2*>(o);
}

// ---------------- layer-2 aggregation (10 chunks of 4 cols per node; simple loop) ----------------
__global__ void agg2_kernel(const float* __restrict__ b2, float* __restrict__ out) {
    int t = blockIdx.x * blockDim.x + threadIdx.x;
    int n = t / 10;
    int c = t % 10;
    if (n >= N_NODES) return;

    int beg = g_rowptr[n];
    int end = g_rowptr[n + 1];

    __half2 h[2];
    *reinterpret_cast<uint2*>(h) =
        *reinterpret_cast<const uint2*>(g_P2h + (size_t)n * N_CLASSES + c * 4);
    float2 f0 = __half22float2(h[0]);
    float2 f1 = __half22float2(h[1]);
    float4 acc = make_float4(f0.x, f0.y, f1.x, f1.y);

    for (int e = beg; e < end; e++) {
        int s = g_cidx[e];
        *reinterpret_cast<uint2*>(h) =
            *reinterpret_cast<const uint2*>(g_P2h + (size_t)s * N_CLASSES + c * 4);
        f0 = __half22float2(h[0]);
        f1 = __half22float2(h[1]);
        acc.x += f0.x; acc.y += f0.y; acc.z += f1.x; acc.w += f1.y;
    }
    float sc = g_dinv[n];
    float4 bb = *reinterpret_cast<const float4*>(b2 + c * 4);
    float4 o;
    o.x = fmaf(acc.x, sc, bb.x);
    o.y = fmaf(acc.y, sc, bb.y);
    o.z = fmaf(acc.z, sc, bb.z);
    o.w = fmaf(acc.w, sc, bb.w);
    *reinterpret_cast<float4*>(out + (size_t)n * N_CLASSES + c * 4) = o;
}

// ---------------- launch ----------------
// Parallel graph branches via stream fork/join:
//   main: wt -> gemm1                               (tensor/smem-bound)
//   side: memset -> hist -> scans -> place -> w2t   (L2-atomic-bound)
// Joined before agg1.
extern "C" void kernel_launch(void* const* d_in, const int* in_sizes, int n_in,
                              void* d_out, int out_size) {
    const float* x  = (const float*)d_in[0];
    const int*   ei = (const int*)d_in[1];     // int32 (JAX x64 disabled)
    const float* W1 = (const float*)d_in[2];
    const float* b1 = (const float*)d_in[3];
    const float* W2 = (const float*)d_in[4];
    const float* b2 = (const float*)d_in[5];
    float* out = (float*)d_out;

    __half *p1, *p2, *x1;
    int* cnt;
    cudaGetSymbolAddress((void**)&p1, g_P1h);
    cudaGetSymbolAddress((void**)&x1, g_X1h);
    cudaGetSymbolAddress((void**)&p2, g_P2h);
    cudaGetSymbolAddress((void**)&cnt, g_cnt);

    const int T = 256;
    const int smem1 = 4 * CHUNKF * sizeof(float);                        // 81920
    const int smem2 = (256 * PITCHA2 + N_CLASSES * PITCH2) * sizeof(float);
    cudaFuncSetAttribute(gemm1_mma_kernel, cudaFuncAttributeMaxDynamicSharedMemorySize, smem1);
    cudaFuncSetAttribute(gemm2_mma_kernel, cudaFuncAttributeMaxDynamicSharedMemorySize, smem2);

    cudaStream_t side;
    cudaStreamCreateWithFlags(&side, cudaStreamNonBlocking);
    cudaEvent_t evFork, evJoin;
    cudaEventCreateWithFlags(&evFork, cudaEventDisableTiming);
    cudaEventCreateWithFlags(&evJoin, cudaEventDisableTiming);

    cudaEventRecord(evFork, 0);
    cudaStreamWaitEvent(side, evFork, 0);

    // side branch: CSR build + dinv + W2 prep
    cudaMemsetAsync(cnt, 0, N_NODES * sizeof(int), side);
    hist_kernel<<<(N_EDGES + T - 1) / T, T, 0, side>>>(ei);
    scan1_kernel<<<NBLK, SCAN_B, 0, side>>>();
    scan2_kernel<<<1, 128, 0, side>>>();
    scan3_kernel<<<(N_NODES + T - 1) / T, T, 0, side>>>();
    place_kernel<<<(N_EDGES + T - 1) / T, T, 0, side>>>(ei);
    w2t_kernel<<<(N_CLASSES * HIDDEN + T - 1) / T, T, 0, side>>>(W2);
    cudaEventRecord(evJoin, side);

    // main branch: W1 prep + layer-1 GEMM
    wt_kernel<<<(HIDDEN * IN_DIM + T - 1) / T, T>>>(W1);
    gemm1_mma_kernel<<<(N_NODES + 127) / 128, 256, smem1>>>(x, p1);

    // join: aggregation needs both branches
    cudaStreamWaitEvent(0, evJoin, 0);

    agg1_kernel<<<(N_NODES * 32 + T - 1) / T, T>>>(b1);
    gemm2_mma_kernel<<<(N_NODES + 255) / 256, 256, smem2>>>(x1, p2);
    agg2_kernel<<<(N_NODES * 10 + T - 1) / T, T>>>(b2, out);
}